// round 15
// baseline (speedup 1.0000x reference)
#include <cuda_runtime.h>
#include <cuda_bf16.h>
#include <stdint.h>

#define DEVINL __device__ __forceinline__

// ---------------------------------------------------------------------------
// Dims: z[N,64] -> h1[N,128] -> h2[N,128] -> b[N,12(pad16)]
// Single-pass tf32 (m16n8k8). W2/W3 k-rows tau-permuted per 8-group.
// Each warp owns 32 rows (2 m-tiles): weight LDSM traffic halved per row.
// Hybrid state: m-tile 1's h1/h2 live in registers; m-tile 0's h1 is staged
// in a warp-private SMEM buffer and re-read via ldmatrix per N-phase.
// ---------------------------------------------------------------------------

// fp32 weight pitches; pitch mod 128B == 16 so ldmatrix rows are conflict-free
static constexpr int P1B = 272;   // W1 k=64  ([128][68] f32)
static constexpr int P2B = 528;   // W2/W3 k=128 ([.][132] f32)
static constexpr int P1  = 68;
static constexpr int P2  = 132;

static constexpr unsigned OFF_W1 = 0;
static constexpr unsigned OFF_W2 = 34816;
static constexpr unsigned OFF_W3 = 102400;
static constexpr unsigned WB     = 110848;

static constexpr unsigned B1O = WB;            // 128 f32
static constexpr unsigned B2O = WB + 512;      // 128 f32
static constexpr unsigned B3O = WB + 1024;     // 16 f32

// h1 staging: per-warp 16 rows x 132 f32 (528B pitch) = 8448B, 8 warps
static constexpr unsigned STPITCH = 528;
static constexpr unsigned STWARP  = 16 * STPITCH;          // 8448
static constexpr unsigned STG0    = 112128;                // 1024-ish aligned
static constexpr unsigned SMT     = STG0 + 8 * STWARP;     // 179712

__device__ __align__(16) unsigned char g_wb[WB];

// ---------------------------------------------------------------------------
DEVINL uint32_t smem_u32(const void* p) {
    uint32_t a;
    asm("{ .reg .u64 t; cvta.to.shared.u64 t, %1; cvt.u32.u64 %0, t; }" : "=r"(a) : "l"(p));
    return a;
}

#define LDSM4(R, ADDR) \
    asm volatile("ldmatrix.sync.aligned.m8n8.x4.shared.b16 {%0,%1,%2,%3},[%4];" \
                 : "=r"((R)[0]), "=r"((R)[1]), "=r"((R)[2]), "=r"((R)[3]) : "r"(ADDR))

#define STS32(ADDR, V) \
    asm volatile("st.shared.b32 [%0], %1;" :: "r"(ADDR), "r"(V))

// tf32 MMA with uint A fragments
#define MMAT(C, A, B0, B1) \
    asm volatile("mma.sync.aligned.m16n8k8.row.col.f32.tf32.tf32.f32 " \
                 "{%0,%1,%2,%3},{%4,%5,%6,%7},{%8,%9},{%0,%1,%2,%3};" \
                 : "+f"((C)[0]), "+f"((C)[1]), "+f"((C)[2]), "+f"((C)[3]) \
                 : "r"((A)[0]), "r"((A)[1]), "r"((A)[2]), "r"((A)[3]), \
                   "r"(B0), "r"(B1))

// tf32 MMA with float-typed A fragments (bit-cast, no move)
#define MMATF(C, A, B0, B1) \
    asm volatile("mma.sync.aligned.m16n8k8.row.col.f32.tf32.tf32.f32 " \
                 "{%0,%1,%2,%3},{%4,%5,%6,%7},{%8,%9},{%0,%1,%2,%3};" \
                 : "+f"((C)[0]), "+f"((C)[1]), "+f"((C)[2]), "+f"((C)[3]) \
                 : "r"(__float_as_uint((A)[0])), "r"(__float_as_uint((A)[1])), \
                   "r"(__float_as_uint((A)[2])), "r"(__float_as_uint((A)[3])), \
                   "r"(B0), "r"(B1))

DEVINL uint32_t cvt_tf32(float f) {
    uint32_t u;
    asm("cvt.rna.tf32.f32 %0, %1;" : "=r"(u) : "f"(f));
    return u;
}

// ---------------------------------------------------------------------------
// prep: weights -> [n][k] tf32-rounded fp32, W2/W3 k-rows tau-permuted
// ---------------------------------------------------------------------------
__global__ void tastenet_prep(const float* __restrict__ W1,
                              const float* __restrict__ W2,
                              const float* __restrict__ W3) {
    int i = blockIdx.x * blockDim.x + threadIdx.x;
    float* w1 = (float*)(g_wb + OFF_W1);
    float* w2 = (float*)(g_wb + OFF_W2);
    float* w3 = (float*)(g_wb + OFF_W3);

    if (i < 128 * 64) {                       // W1 (64,128) -> [n][k], natural
        int n = i >> 6, k = i & 63;
        uint32_t u = cvt_tf32(W1[k * 128 + n]);
        w1[n * P1 + k] = __uint_as_float(u);
    }
    if (i < 128 * 128) {                      // W2 (128,128) -> [n][p], k=tau(p)
        int n = i >> 7, p = i & 127;
        int pg = p & 7;
        int kl = (pg < 4) ? (2 * pg) : (2 * (pg - 4) + 1);
        int k = (p & ~7) + kl;
        uint32_t u = cvt_tf32(W2[k * 128 + n]);
        w2[n * P2 + p] = __uint_as_float(u);
    }
    if (i < 16 * 128) {                       // W3 (128,12) pad n to 16
        int n = i >> 7, p = i & 127;
        int pg = p & 7;
        int kl = (pg < 4) ? (2 * pg) : (2 * (pg - 4) + 1);
        int k = (p & ~7) + kl;
        float w = (n < 12) ? W3[k * 12 + n] : 0.f;
        uint32_t u = cvt_tf32(w);
        w3[n * P2 + p] = __uint_as_float(u);
    }
}

// ---------------------------------------------------------------------------
// main persistent kernel: 256 threads, each warp independently owns 32 rows
// (2 m-tiles) per super-tile of 256 rows.
// ---------------------------------------------------------------------------
__global__ void __launch_bounds__(256, 1)
tastenet_main(const float* __restrict__ x, const float* __restrict__ z,
              const float* __restrict__ b1, const float* __restrict__ b2,
              const float* __restrict__ b3, float* __restrict__ out,
              int num_st) {
    extern __shared__ __align__(16) unsigned char smem[];
    const int tid = threadIdx.x;

    // ---- one-time: copy weight image + biases into smem ----
    {
        const float4* s = reinterpret_cast<const float4*>(g_wb);
        float4* d = reinterpret_cast<float4*>(smem);
        for (int i = tid; i < (int)(WB / 16); i += 256) d[i] = s[i];
        float* sb1 = (float*)(smem + B1O);
        float* sb2 = (float*)(smem + B2O);
        float* sb3 = (float*)(smem + B3O);
        if (tid < 128) { sb1[tid] = b1[tid]; sb2[tid] = b2[tid]; }
        if (tid < 16)  sb3[tid] = (tid < 12) ? b3[tid] : 0.f;
    }
    __syncthreads();

    const uint32_t sb = smem_u32(smem);
    const int w = tid >> 5, l = tid & 31;
    const int g = l >> 2, q = l & 3;

    // B-operand ldmatrix lane bases (tf32-pair trick: row l&7, float-col 4*(l>>3))
    const uint32_t bW1 = sb + OFF_W1 + (l & 7) * P1B + (l >> 3) * 16;
    const uint32_t bW2 = sb + OFF_W2 + (l & 7) * P2B + (l >> 3) * 16;
    const uint32_t bW3 = sb + OFF_W3 + (l & 7) * P2B + (l >> 3) * 16;

    // staging: write base (this thread's rows g / g+8), ldmatrix read base
    const uint32_t stBase = sb + STG0 + (unsigned)w * STWARP;
    const uint32_t stW0 = stBase + (unsigned)g * STPITCH;            // row g
    const uint32_t stW8 = stW0 + 8u * STPITCH;                        // row g+8
    // A-operand ldmatrix lane map: row (l&7)+8*((l>>3)&1), fcol 4*(l>>4)
    const uint32_t stR = stBase + ((unsigned)((l & 7) + (((l >> 3) & 1) << 3))) * STPITCH
                        + ((unsigned)(l >> 4)) * 16u;

    const float* sb3 = (const float*)(smem + B3O);
    const unsigned char* b1p = smem + B1O;
    const unsigned char* b2p = smem + B2O;

    for (int st = blockIdx.x; st < num_st; st += gridDim.x) {
        const int base = st * 256 + w * 32;   // warp's first row

        // ---- layer 1: K=64, N=128, both m-tiles, shared B loads ----
        float acc[16][2][4];
#pragma unroll
        for (int n = 0; n < 16; n++)
#pragma unroll
            for (int mt = 0; mt < 2; mt++)
#pragma unroll
                for (int c = 0; c < 4; c++) acc[n][mt][c] = 0.f;

#pragma unroll
        for (int kp = 0; kp < 4; kp++) {
            // A fragments for this k=16 chunk, straight from gmem z
            uint32_t A1[2][2][4];
#pragma unroll
            for (int mt = 0; mt < 2; mt++) {
                const float* z0 = z + (size_t)(base + mt * 16 + g) * 64 + q + kp * 16;
                const float* z8 = z0 + 8 * 64;
#pragma unroll
                for (int kt = 0; kt < 2; kt++) {
                    A1[kt][mt][0] = cvt_tf32(z0[8 * kt]);
                    A1[kt][mt][1] = cvt_tf32(z8[8 * kt]);
                    A1[kt][mt][2] = cvt_tf32(z0[8 * kt + 4]);
                    A1[kt][mt][3] = cvt_tf32(z8[8 * kt + 4]);
                }
            }
#pragma unroll
            for (int jb = 0; jb < 4; jb++) {
                uint32_t B[4][4];
#pragma unroll
                for (int j = 0; j < 4; j++)
                    LDSM4(B[j], bW1 + (4 * jb + j) * 8 * P1B + kp * 64);
#pragma unroll
                for (int j = 0; j < 4; j++)
#pragma unroll
                    for (int mt = 0; mt < 2; mt++)
                        MMAT(acc[4 * jb + j][mt], A1[0][mt], B[j][0], B[j][1]);
#pragma unroll
                for (int j = 0; j < 4; j++)
#pragma unroll
                    for (int mt = 0; mt < 2; mt++)
                        MMAT(acc[4 * jb + j][mt], A1[1][mt], B[j][2], B[j][3]);
            }
        }

        // ---- transition h1 = relu(acc+b1) ----
        // m-tile 0 -> SMEM staging (tau_inv cols: 2q->q, 2q+1->q+4)
        // m-tile 1 -> in-place tau swap (stays in registers)
#pragma unroll
        for (int np = 0; np < 16; np++) {
            float2 bb = *(const float2*)(b1p + (8 * np + 2 * q) * 4);
            {   // m-tile 0 -> staging
                float v0 = fmaxf(acc[np][0][0] + bb.x, 0.f);
                float v1 = fmaxf(acc[np][0][1] + bb.y, 0.f);
                float v2 = fmaxf(acc[np][0][2] + bb.x, 0.f);
                float v3 = fmaxf(acc[np][0][3] + bb.y, 0.f);
                uint32_t cbyte = (unsigned)(8 * np + q) * 4u;
                STS32(stW0 + cbyte,       cvt_tf32(v0));
                STS32(stW0 + cbyte + 16u, cvt_tf32(v1));
                STS32(stW8 + cbyte,       cvt_tf32(v2));
                STS32(stW8 + cbyte + 16u, cvt_tf32(v3));
            }
            {   // m-tile 1 -> registers (tau: c1<->c2 swap)
                float v0 = fmaxf(acc[np][1][0] + bb.x, 0.f);
                float v1 = fmaxf(acc[np][1][1] + bb.y, 0.f);
                float v2 = fmaxf(acc[np][1][2] + bb.x, 0.f);
                float v3 = fmaxf(acc[np][1][3] + bb.y, 0.f);
                acc[np][1][0] = __uint_as_float(cvt_tf32(v0));
                acc[np][1][1] = __uint_as_float(cvt_tf32(v2));
                acc[np][1][2] = __uint_as_float(cvt_tf32(v1));
                acc[np][1][3] = __uint_as_float(cvt_tf32(v3));
            }
        }
        __syncwarp();   // staging visible to all lanes before ldmatrix

        // ---- layer-3 accumulators (filled incrementally per phase) ----
        float a3[2][2][4];
#pragma unroll
        for (int mt = 0; mt < 2; mt++)
#pragma unroll
            for (int n = 0; n < 2; n++)
#pragma unroll
                for (int c = 0; c < 4; c++) a3[mt][n][c] = 0.f;

        // ---- layer 2 in four N=32 phases + partial layer 3 per phase ----
#pragma unroll 1
        for (int h = 0; h < 4; h++) {
            const uint32_t bW2p = bW2 + (unsigned)h * 4u * 8u * P2B;
            const uint32_t bW3p = bW3 + (unsigned)h * 128u;
            const unsigned char* b2pp = b2p + h * 128;

            float ap[4][2][4];
#pragma unroll
            for (int n = 0; n < 4; n++)
#pragma unroll
                for (int mt = 0; mt < 2; mt++)
#pragma unroll
                    for (int c = 0; c < 4; c++) ap[n][mt][c] = 0.f;

#pragma unroll
            for (int kp = 0; kp < 8; kp++) {
                // m-tile 0 A fragments from staging (2 k-tiles per kp)
                uint32_t A0e[4], A0o[4];
                LDSM4(A0e, stR + (unsigned)kp * 64u);
                LDSM4(A0o, stR + (unsigned)kp * 64u + 32u);
#pragma unroll
                for (int jb = 0; jb < 2; jb++) {
                    uint32_t B[2][4];
#pragma unroll
                    for (int j = 0; j < 2; j++)
                        LDSM4(B[j], bW2p + (2 * jb + j) * 8 * P2B + kp * 64);
#pragma unroll
                    for (int j = 0; j < 2; j++) {
                        MMAT (ap[2 * jb + j][0], A0e,            B[j][0], B[j][1]);
                        MMATF(ap[2 * jb + j][1], acc[2 * kp][1], B[j][0], B[j][1]);
                    }
#pragma unroll
                    for (int j = 0; j < 2; j++) {
                        MMAT (ap[2 * jb + j][0], A0o,                B[j][2], B[j][3]);
                        MMATF(ap[2 * jb + j][1], acc[2 * kp + 1][1], B[j][2], B[j][3]);
                    }
                }
            }

            // relu(ap+b2) -> A3 frags, IN PLACE (tau swap)
#pragma unroll
            for (int j = 0; j < 4; j++) {
                float2 bb = *(const float2*)(b2pp + (8 * j + 2 * q) * 4);
#pragma unroll
                for (int mt = 0; mt < 2; mt++) {
                    float v0 = fmaxf(ap[j][mt][0] + bb.x, 0.f);
                    float v1 = fmaxf(ap[j][mt][1] + bb.y, 0.f);
                    float v2 = fmaxf(ap[j][mt][2] + bb.x, 0.f);
                    float v3 = fmaxf(ap[j][mt][3] + bb.y, 0.f);
                    ap[j][mt][0] = __uint_as_float(cvt_tf32(v0));
                    ap[j][mt][1] = __uint_as_float(cvt_tf32(v2));
                    ap[j][mt][2] = __uint_as_float(cvt_tf32(v1));
                    ap[j][mt][3] = __uint_as_float(cvt_tf32(v3));
                }
            }

            // partial layer 3 over this k-quarter, then ap dies
#pragma unroll
            for (int kpl = 0; kpl < 2; kpl++) {
                uint32_t B0[4], B1r[4];
                LDSM4(B0,  bW3p + kpl * 64);
                LDSM4(B1r, bW3p + 8 * P2B + kpl * 64);
#pragma unroll
                for (int mt = 0; mt < 2; mt++) {
                    MMATF(a3[mt][0], ap[2 * kpl][mt],     B0[0],  B0[1]);
                    MMATF(a3[mt][1], ap[2 * kpl][mt],     B1r[0], B1r[1]);
                    MMATF(a3[mt][0], ap[2 * kpl + 1][mt], B0[2],  B0[3]);
                    MMATF(a3[mt][1], ap[2 * kpl + 1][mt], B1r[2], B1r[3]);
                }
            }
        }

        // ---- epilogue per m-tile: clamps, taste*x segment sums, store ----
#pragma unroll
        for (int mt = 0; mt < 2; mt++) {
            float b3A = sb3[2 * q], b3B = sb3[2 * q + 1];
            float b3C = sb3[8 + 2 * q], b3D = sb3[9 + 2 * q];
            const int row0 = base + mt * 16 + g;
#pragma unroll
            for (int rs = 0; rs < 2; rs++) {
                float vA = a3[mt][0][rs * 2 + 0] + b3A;   // col 2q
                float vB = a3[mt][0][rs * 2 + 1] + b3B;   // col 2q+1
                float vC = a3[mt][1][rs * 2 + 0] + b3C;   // col 8+2q
                float vD = a3[mt][1][rs * 2 + 1] + b3D;   // col 9+2q
                if (q < 3)  vA = fminf(vA, 0.f);
                vB = fminf(vB, 0.f);
                if (q == 0) vC = fminf(vC, 0.f);

                int row = row0 + rs * 8;
                const float* xr = x + (size_t)row * 9;
                float l0 = xr[q];
                float l1 = xr[4 + q];
                float l2 = xr[8];

                unsigned basel = (unsigned)(l & ~3);
                float xAl = __shfl_sync(0xffffffffu, l0, basel | ((2 * q) & 3));
                float xAh = __shfl_sync(0xffffffffu, l1, basel | ((2 * q) & 3));
                float xBl = __shfl_sync(0xffffffffu, l0, basel | ((2 * q + 1) & 3));
                float xBh = __shfl_sync(0xffffffffu, l1, basel | ((2 * q + 1) & 3));
                float xA = (q < 2) ? xAl : xAh;
                float xB = (q < 2) ? xBl : xBh;

                float p0 = 0.f, p1 = 0.f, p2 = 0.f;
                if (q == 0) {
                    p0 = fmaf(xA, vA, xB * vB) + vD;
                    p2 = l2 * vC;
                } else if (q == 1) {
                    p0 = xA * vA;
                    p1 = xB * vB + vC;
                    p2 = vD;
                } else if (q == 2) {
                    p1 = fmaf(xA, vA, xB * vB);
                } else {
                    p2 = fmaf(xA, vA, xB * vB);
                }
                p0 += __shfl_xor_sync(0xffffffffu, p0, 1);
                p0 += __shfl_xor_sync(0xffffffffu, p0, 2);
                p1 += __shfl_xor_sync(0xffffffffu, p1, 1);
                p1 += __shfl_xor_sync(0xffffffffu, p1, 2);
                p2 += __shfl_xor_sync(0xffffffffu, p2, 1);
                p2 += __shfl_xor_sync(0xffffffffu, p2, 2);
                if (q < 3) {
                    float val = (q == 0) ? p0 : (q == 1) ? p1 : p2;
                    out[(size_t)row * 3 + q] = val;
                }
            }
        }
        __syncwarp();   // all lanes done with staging before next iteration
    }
}

// ---------------------------------------------------------------------------
// kernel_launch
// ---------------------------------------------------------------------------
extern "C" void kernel_launch(void* const* d_in, const int* in_sizes, int n_in,
                              void* d_out, int out_size) {
    const float* x  = (const float*)d_in[0];
    const float* z  = (const float*)d_in[1];
    const float* W1 = (const float*)d_in[2];
    const float* b1 = (const float*)d_in[3];
    const float* W2 = (const float*)d_in[4];
    const float* b2 = (const float*)d_in[5];
    const float* W3 = (const float*)d_in[6];
    const float* b3 = (const float*)d_in[7];
    float* out = (float*)d_out;

    const int n = in_sizes[1] / 64;
    const int num_st = n / 256;              // 256-row super-tiles

    tastenet_prep<<<64, 256>>>(W1, W2, W3);

    static int smem_set = 0;
    if (!smem_set) {
        cudaFuncSetAttribute(tastenet_main,
                             cudaFuncAttributeMaxDynamicSharedMemorySize, SMT);
        smem_set = 1;
    }
    int dev = 0, sms = 148;
    cudaGetDevice(&dev);
    cudaDeviceGetAttribute(&sms, cudaDevAttrMultiProcessorCount, dev);
    int grid = (sms < num_st) ? sms : num_st;
    if (grid < 1) grid = 1;

    tastenet_main<<<grid, 256, SMT>>>(x, z, b1, b2, b3, out, num_st);
}

// round 16
// speedup vs baseline: 1.9980x; 1.9980x over previous
#include <cuda_runtime.h>
#include <cuda_fp16.h>
#include <stdint.h>

#define DEVINL __device__ __forceinline__

// ---------------------------------------------------------------------------
// Dims: z[N,64] -> h1[N,128] -> h2[N,128] -> b[N,12(pad16)] ; tile M=128
// Single-pass fp16 (m16n8k16, fp32 accumulate). fp16 mantissa (11 bits incl
// implicit) == tf32 precision, but k16 doubles MACs/instr and halves weight
// bytes. Each warp owns 16 rows; transitions stay register-only: the k16
// accumulator n-tile pair {2j,2j+1} maps directly onto A-frag {klow,khigh}.
// ---------------------------------------------------------------------------

// fp16 weight pitches (elems / bytes); pitch mod 128B == 16 -> conflict-free
static constexpr int PZ  = 72;   static constexpr int PZB = 144;   // W1 k=64
static constexpr int PH  = 136;  static constexpr int PHB = 272;   // W2/W3 k=128

static constexpr unsigned OFF_W1 = 0;                      // [128][72] f16
static constexpr unsigned OFF_W2 = 18432;                  // [128][136] f16
static constexpr unsigned OFF_W3 = 53248;                  // [16][136] f16
static constexpr unsigned WB     = 57600;

// raw z staging: 128 rows x 68 floats (272B pitch), double buffered
static constexpr unsigned ZPITCH = 272;
static constexpr unsigned ZRSZ   = 128 * ZPITCH;           // 34816
static constexpr unsigned ZR0    = WB;                     // 57600
static constexpr unsigned B1O    = ZR0 + 2 * ZRSZ;         // 127232
static constexpr unsigned B2O    = B1O + 512;
static constexpr unsigned B3O    = B2O + 512;
static constexpr unsigned SMT    = B3O + 64;               // 128320

__device__ __align__(16) unsigned char g_wb[WB];

// ---------------------------------------------------------------------------
DEVINL uint32_t smem_u32(const void* p) {
    uint32_t a;
    asm("{ .reg .u64 t; cvta.to.shared.u64 t, %1; cvt.u32.u64 %0, t; }" : "=r"(a) : "l"(p));
    return a;
}

#define LDSM4(R, ADDR) \
    asm volatile("ldmatrix.sync.aligned.m8n8.x4.shared.b16 {%0,%1,%2,%3},[%4];" \
                 : "=r"((R)[0]), "=r"((R)[1]), "=r"((R)[2]), "=r"((R)[3]) : "r"(ADDR))

// fp16 MMA, fp32 accumulate: D[16x8] += A[16x16] * B[16x8]
#define MMAH(C, A, B0, B1) \
    asm volatile("mma.sync.aligned.m16n8k16.row.col.f32.f16.f16.f32 " \
                 "{%0,%1,%2,%3},{%4,%5,%6,%7},{%8,%9},{%0,%1,%2,%3};" \
                 : "+f"((C)[0]), "+f"((C)[1]), "+f"((C)[2]), "+f"((C)[3]) \
                 : "r"((A)[0]), "r"((A)[1]), "r"((A)[2]), "r"((A)[3]), \
                   "r"(B0), "r"(B1))

#define CP_ASYNC16(DST, SRC) \
    asm volatile("cp.async.cg.shared.global [%0], [%1], 16;" :: "r"(DST), "l"(SRC))
#define CP_COMMIT() asm volatile("cp.async.commit_group;")
#define CP_WAIT0()  asm volatile("cp.async.wait_group 0;" ::: "memory")

DEVINL uint32_t pkh2(float a, float b) {
    __half2 h = __floats2half2_rn(a, b);
    return *reinterpret_cast<uint32_t*>(&h);
}

// ---------------------------------------------------------------------------
// prep: weights -> [n][k] fp16, padded pitch (natural k order; no permutation)
// ---------------------------------------------------------------------------
__global__ void tastenet_prep(const float* __restrict__ W1,
                              const float* __restrict__ W2,
                              const float* __restrict__ W3) {
    int i = blockIdx.x * blockDim.x + threadIdx.x;
    __half* w1 = (__half*)(g_wb + OFF_W1);
    __half* w2 = (__half*)(g_wb + OFF_W2);
    __half* w3 = (__half*)(g_wb + OFF_W3);

    if (i < 128 * 64) {                       // W1 (64,128) -> [n][k]
        int n = i >> 6, k = i & 63;
        w1[n * PZ + k] = __float2half(W1[k * 128 + n]);
    }
    if (i < 128 * 128) {                      // W2 (128,128) -> [n][k]
        int n = i >> 7, k = i & 127;
        w2[n * PH + k] = __float2half(W2[k * 128 + n]);
    }
    if (i < 16 * 128) {                       // W3 (128,12) pad n to 16
        int n = i >> 7, k = i & 127;
        float w = (n < 12) ? W3[k * 12 + n] : 0.f;
        w3[n * PH + k] = __float2half(w);
    }
}

// ---------------------------------------------------------------------------
// main persistent kernel: 256 threads, each warp owns 16 rows per tile
// ---------------------------------------------------------------------------
__global__ void __launch_bounds__(256, 1)
tastenet_main(const float* __restrict__ x, const float* __restrict__ z,
              const float* __restrict__ b1, const float* __restrict__ b2,
              const float* __restrict__ b3, float* __restrict__ out,
              int num_tiles) {
    extern __shared__ __align__(16) unsigned char smem[];
    const int tid = threadIdx.x;

    // ---- one-time: copy weight image + biases into smem ----
    {
        const float4* s = reinterpret_cast<const float4*>(g_wb);
        float4* d = reinterpret_cast<float4*>(smem);
        for (int i = tid; i < (int)(WB / 16); i += 256) d[i] = s[i];
        float* sb1 = (float*)(smem + B1O);
        float* sb2 = (float*)(smem + B2O);
        float* sb3 = (float*)(smem + B3O);
        if (tid < 128) { sb1[tid] = b1[tid]; sb2[tid] = b2[tid]; }
        if (tid < 16)  sb3[tid] = (tid < 12) ? b3[tid] : 0.f;
    }
    __syncthreads();

    const uint32_t sb = smem_u32(smem);
    const int w = tid >> 5, l = tid & 31;
    const int g = l >> 2, q = l & 3;
    const int m0 = w * 16;
    const int qq = l >> 3, rr = l & 7;

    // B-operand ldmatrix lane bases: rows n 0-7/8-15, k-halves 16B
    const int brow = ((qq >> 1) << 3) + rr;
    const int bkof = (qq & 1) << 4;
    const uint32_t bW1 = sb + OFF_W1 + brow * PZB + bkof;
    const uint32_t bW2 = sb + OFF_W2 + brow * PHB + bkof;
    const uint32_t bW3 = sb + OFF_W3 + brow * PHB + bkof;

    const float* sb3 = (const float*)(smem + B3O);
    const unsigned char* b1p = smem + B1O;
    const unsigned char* b2p = smem + B2O;

    // cp.async lane mapping: 8 x 16B per thread covers this warp's 16 rows
    const int zrow = l >> 4;
    const int zcol = l & 15;

    int t = blockIdx.x;
    int pbuf = 0;
    {
#pragma unroll
        for (int j = 0; j < 8; j++) {
            int row = m0 + j * 2 + zrow;
            uint32_t dst = sb + ZR0 + row * ZPITCH + zcol * 16;
            const float* src = z + ((size_t)t * 128 + row) * 64 + zcol * 4;
            CP_ASYNC16(dst, src);
        }
        CP_COMMIT();
    }

    for (; t < num_tiles; t += gridDim.x) {
        CP_WAIT0();
        __syncwarp();

        // ---- build layer-1 A fragments (fp16 pairs) from staged fp32 z ----
        uint32_t A1[4][4];
        {
            const unsigned char* r0p = smem + ZR0 + pbuf * ZRSZ + (m0 + g) * ZPITCH;
            const unsigned char* r8p = r0p + 8 * ZPITCH;
#pragma unroll
            for (int kt = 0; kt < 4; kt++) {
                float2 vl0 = *(const float2*)(r0p + (8 * kt + q) * 8);
                float2 vl8 = *(const float2*)(r8p + (8 * kt + q) * 8);
                float2 vh0 = *(const float2*)(r0p + (8 * kt + q + 4) * 8);
                float2 vh8 = *(const float2*)(r8p + (8 * kt + q + 4) * 8);
                A1[kt][0] = pkh2(vl0.x, vl0.y);   // row g,   k-low
                A1[kt][1] = pkh2(vl8.x, vl8.y);   // row g+8, k-low
                A1[kt][2] = pkh2(vh0.x, vh0.y);   // row g,   k-high
                A1[kt][3] = pkh2(vh8.x, vh8.y);   // row g+8, k-high
            }
        }

        // ---- prefetch next tile's z into the other buffer ----
        if (t + (int)gridDim.x < num_tiles) {
            int tn = t + gridDim.x;
            uint32_t zb = sb + ZR0 + (pbuf ^ 1) * ZRSZ;
#pragma unroll
            for (int j = 0; j < 8; j++) {
                int row = m0 + j * 2 + zrow;
                uint32_t dst = zb + row * ZPITCH + zcol * 16;
                const float* src = z + ((size_t)tn * 128 + row) * 64 + zcol * 4;
                CP_ASYNC16(dst, src);
            }
            CP_COMMIT();
        }

        // ---- prefetch x for the epilogue ----
        const int row0 = t * 128 + m0 + g;
        float xp[2][3];
#pragma unroll
        for (int rs = 0; rs < 2; rs++) {
            const float* xr = x + (size_t)(row0 + rs * 8) * 9;
            xp[rs][0] = xr[q];
            xp[rs][1] = xr[4 + q];
            xp[rs][2] = xr[8];
        }

        float acc[16][4];
#pragma unroll
        for (int n = 0; n < 16; n++)
#pragma unroll
            for (int c = 0; c < 4; c++) acc[n][c] = 0.f;

        // ---- layer 1: K=64 (4 k-tiles of 16) ----
#pragma unroll
        for (int kt = 0; kt < 4; kt++) {
#pragma unroll
            for (int np2 = 0; np2 < 8; np2++) {
                uint32_t B[4];
                LDSM4(B, bW1 + np2 * 16 * PZB + kt * 32);
                MMAH(acc[2 * np2],     A1[kt], B[0], B[1]);
                MMAH(acc[2 * np2 + 1], A1[kt], B[2], B[3]);
            }
        }

        // ---- h1 = relu(acc+b1) -> A2 fp16 frags (registers only) ----
        uint32_t A2[8][4];
#pragma unroll
        for (int j = 0; j < 8; j++) {
            float2 bA = *(const float2*)(b1p + (16 * j + 2 * q) * 4);
            float2 bB = *(const float2*)(b1p + (16 * j + 8 + 2 * q) * 4);
            float v0 = fmaxf(acc[2 * j][0] + bA.x, 0.f);
            float v1 = fmaxf(acc[2 * j][1] + bA.y, 0.f);
            float v2 = fmaxf(acc[2 * j][2] + bA.x, 0.f);
            float v3 = fmaxf(acc[2 * j][3] + bA.y, 0.f);
            float u0 = fmaxf(acc[2 * j + 1][0] + bB.x, 0.f);
            float u1 = fmaxf(acc[2 * j + 1][1] + bB.y, 0.f);
            float u2 = fmaxf(acc[2 * j + 1][2] + bB.x, 0.f);
            float u3 = fmaxf(acc[2 * j + 1][3] + bB.y, 0.f);
            A2[j][0] = pkh2(v0, v1);   // row g,   k-low
            A2[j][1] = pkh2(v2, v3);   // row g+8, k-low
            A2[j][2] = pkh2(u0, u1);   // row g,   k-high
            A2[j][3] = pkh2(u2, u3);   // row g+8, k-high
        }

#pragma unroll
        for (int n = 0; n < 16; n++)
#pragma unroll
            for (int c = 0; c < 4; c++) acc[n][c] = 0.f;

        // ---- layer 2: K=128 (8 k-tiles) ----
#pragma unroll
        for (int kt = 0; kt < 8; kt++) {
#pragma unroll
            for (int np2 = 0; np2 < 8; np2++) {
                uint32_t B[4];
                LDSM4(B, bW2 + np2 * 16 * PHB + kt * 32);
                MMAH(acc[2 * np2],     A2[kt], B[0], B[1]);
                MMAH(acc[2 * np2 + 1], A2[kt], B[2], B[3]);
            }
        }

        // ---- h2 = relu(acc+b2) -> A frags (reuse A2) ----
#pragma unroll
        for (int j = 0; j < 8; j++) {
            float2 bA = *(const float2*)(b2p + (16 * j + 2 * q) * 4);
            float2 bB = *(const float2*)(b2p + (16 * j + 8 + 2 * q) * 4);
            float v0 = fmaxf(acc[2 * j][0] + bA.x, 0.f);
            float v1 = fmaxf(acc[2 * j][1] + bA.y, 0.f);
            float v2 = fmaxf(acc[2 * j][2] + bA.x, 0.f);
            float v3 = fmaxf(acc[2 * j][3] + bA.y, 0.f);
            float u0 = fmaxf(acc[2 * j + 1][0] + bB.x, 0.f);
            float u1 = fmaxf(acc[2 * j + 1][1] + bB.y, 0.f);
            float u2 = fmaxf(acc[2 * j + 1][2] + bB.x, 0.f);
            float u3 = fmaxf(acc[2 * j + 1][3] + bB.y, 0.f);
            A2[j][0] = pkh2(v0, v1);
            A2[j][1] = pkh2(v2, v3);
            A2[j][2] = pkh2(u0, u1);
            A2[j][3] = pkh2(u2, u3);
        }

        // ---- layer 3: [128] -> 16, even/odd acc sets for dep distance ----
        float a3e[2][4], a3o[2][4];
#pragma unroll
        for (int n = 0; n < 2; n++)
#pragma unroll
            for (int c = 0; c < 4; c++) { a3e[n][c] = 0.f; a3o[n][c] = 0.f; }
#pragma unroll
        for (int kt = 0; kt < 8; kt++) {
            uint32_t B[4];
            LDSM4(B, bW3 + kt * 32);
            if (kt & 1) {
                MMAH(a3o[0], A2[kt], B[0], B[1]);
                MMAH(a3o[1], A2[kt], B[2], B[3]);
            } else {
                MMAH(a3e[0], A2[kt], B[0], B[1]);
                MMAH(a3e[1], A2[kt], B[2], B[3]);
            }
        }
        float a3[2][4];
#pragma unroll
        for (int n = 0; n < 2; n++)
#pragma unroll
            for (int c = 0; c < 4; c++) a3[n][c] = a3e[n][c] + a3o[n][c];

        // ---- epilogue: clamps, taste*x segment sums via quad shuffles ----
        {
            float b3A = sb3[2 * q], b3B = sb3[2 * q + 1];
            float b3C = sb3[8 + 2 * q], b3D = sb3[9 + 2 * q];
#pragma unroll
            for (int rs = 0; rs < 2; rs++) {
                float vA = a3[0][rs * 2 + 0] + b3A;   // col 2q
                float vB = a3[0][rs * 2 + 1] + b3B;   // col 2q+1
                float vC = a3[1][rs * 2 + 0] + b3C;   // col 8+2q
                float vD = a3[1][rs * 2 + 1] + b3D;   // col 9+2q
                if (q < 3)  vA = fminf(vA, 0.f);      // cols 0,2,4 clamp; col6 raw
                vB = fminf(vB, 0.f);                  // cols 1,3,5,7 clamp
                if (q == 0) vC = fminf(vC, 0.f);      // col 8 clamp

                int row = row0 + rs * 8;
                float l0 = xp[rs][0];
                float l1 = xp[rs][1];
                float l2 = xp[rs][2];

                unsigned basel = (unsigned)(l & ~3);
                float xAl = __shfl_sync(0xffffffffu, l0, basel | ((2 * q) & 3));
                float xAh = __shfl_sync(0xffffffffu, l1, basel | ((2 * q) & 3));
                float xBl = __shfl_sync(0xffffffffu, l0, basel | ((2 * q + 1) & 3));
                float xBh = __shfl_sync(0xffffffffu, l1, basel | ((2 * q + 1) & 3));
                float xA = (q < 2) ? xAl : xAh;
                float xB = (q < 2) ? xBl : xBh;

                float p0 = 0.f, p1 = 0.f, p2 = 0.f;
                if (q == 0) {
                    p0 = fmaf(xA, vA, xB * vB) + vD;  // x0*t0 + x1*t1 + i0
                    p2 = l2 * vC;                      // x8*t8
                } else if (q == 1) {
                    p0 = xA * vA;                      // x2*t2
                    p1 = xB * vB + vC;                 // x3*t3 + i1
                    p2 = vD;                           // i2
                } else if (q == 2) {
                    p1 = fmaf(xA, vA, xB * vB);        // x4*t4 + x5*t5
                } else {
                    p2 = fmaf(xA, vA, xB * vB);        // x6*t6 + x7*t7
                }
                p0 += __shfl_xor_sync(0xffffffffu, p0, 1);
                p0 += __shfl_xor_sync(0xffffffffu, p0, 2);
                p1 += __shfl_xor_sync(0xffffffffu, p1, 1);
                p1 += __shfl_xor_sync(0xffffffffu, p1, 2);
                p2 += __shfl_xor_sync(0xffffffffu, p2, 1);
                p2 += __shfl_xor_sync(0xffffffffu, p2, 2);
                if (q < 3) {
                    float val = (q == 0) ? p0 : (q == 1) ? p1 : p2;
                    out[(size_t)row * 3 + q] = val;
                }
            }
        }
        pbuf ^= 1;
    }
}

// ---------------------------------------------------------------------------
// kernel_launch
// ---------------------------------------------------------------------------
extern "C" void kernel_launch(void* const* d_in, const int* in_sizes, int n_in,
                              void* d_out, int out_size) {
    const float* x  = (const float*)d_in[0];
    const float* z  = (const float*)d_in[1];
    const float* W1 = (const float*)d_in[2];
    const float* b1 = (const float*)d_in[3];
    const float* W2 = (const float*)d_in[4];
    const float* b2 = (const float*)d_in[5];
    const float* W3 = (const float*)d_in[6];
    const float* b3 = (const float*)d_in[7];
    float* out = (float*)d_out;

    const int n = in_sizes[1] / 64;
    const int num_tiles = n / 128;

    tastenet_prep<<<64, 256>>>(W1, W2, W3);

    static int smem_set = 0;
    if (!smem_set) {
        cudaFuncSetAttribute(tastenet_main,
                             cudaFuncAttributeMaxDynamicSharedMemorySize, SMT);
        smem_set = 1;
    }
    int dev = 0, sms = 148;
    cudaGetDevice(&dev);
    cudaDeviceGetAttribute(&sms, cudaDevAttrMultiProcessorCount, dev);
    int grid = (sms < num_tiles) ? sms : num_tiles;
    if (grid < 1) grid = 1;

    tastenet_main<<<grid, 256, SMT>>>(x, z, b1, b2, b3, out, num_tiles);
}